// round 13
// baseline (speedup 1.0000x reference)
#include <cuda_runtime.h>
#include <cuda_fp8.h>
#include <math.h>
#include <stdint.h>

// Shape (fixed by dataset): N=65536, P=2048, D=64, 10 classes.
#define NPTS 65536
#define PPTS 2048
#define DDIM 64
#define BM 256               // two 128-row x-tiles per CTA
#define BN 128
#define ROWB 80              // bytes per padded fp8 row (64 data + 16 pad)
#define NTILES (PPTS / BN)   // 16
#define NBLOCKS (NPTS / BM)  // 256
#define BTILE (BN * ROWB)    // 10240 bytes per B buffer

// __device__ scratch (allocation-free rule). Prototypes staged as e4m3.
__device__ __align__(16) unsigned char g_pb[PPTS * DDIM];
__device__ __align__(16) float g_p2[PPTS];
__device__ float g_partial[NBLOCKS];
__device__ unsigned int g_count;   // zero-init; last block resets

// Dynamic smem layout (bytes)
#define SM_B0    0                 // B tile buffer (even t)          10240
#define SM_AB1   10240             // x staging, then B buffer (odd)  10240
#define SM_PP2   20480             // 2 bufs x 128 f32                 1024
#define SM_PPL   21504             // 2 bufs x 128 i32                 1024
#define SM_RED   22528             // [2 wn][2][256] f32               8192
#define SM_XS2   30720             // 256 f32 row norms                1024
#define SM_RSUM  31744             // 8 f32
#define SM_FLAG  31776
#define SM_TOTAL 31808

__device__ __forceinline__ void cp16(uint32_t dst, const void* src) {
    asm volatile("cp.async.cg.shared.global [%0], [%1], 16;\n" :: "r"(dst), "l"(src));
}
#define CP_COMMIT() asm volatile("cp.async.commit_group;\n" ::: "memory")
#define CP_WAIT(n)  asm volatile("cp.async.wait_group %0;\n" :: "n"(n) : "memory")

__device__ __forceinline__ uint32_t padoff(int idx) {     // idx-th 16B chunk (4/row)
    return (uint32_t)((idx >> 2) * ROWB + (idx & 3) * 16);
}
// pack 4 floats -> 4 e4m3 bytes in one uint32 (k order)
__device__ __forceinline__ uint32_t pk8(float a, float b, float c, float d) {
    __nv_fp8x2_storage_t lo = __nv_cvt_float2_to_fp8x2(make_float2(a, b),
                                                       __NV_SATFINITE, __NV_E4M3);
    __nv_fp8x2_storage_t hi = __nv_cvt_float2_to_fp8x2(make_float2(c, d),
                                                       __NV_SATFINITE, __NV_E4M3);
    return (uint32_t)lo | ((uint32_t)hi << 16);
}
#define LDSMX4(rr, addr) asm volatile( \
    "ldmatrix.sync.aligned.m8n8.x4.shared.b16 {%0,%1,%2,%3}, [%4];\n" \
    : "=r"((rr)[0]), "=r"((rr)[1]), "=r"((rr)[2]), "=r"((rr)[3]) : "r"(addr))
// e4m3 x e4m3 -> f32, K=32 per instruction
#define MMAFP8(cc, aa, b0, b1) asm volatile( \
    "mma.sync.aligned.m16n8k32.row.col.f32.e4m3.e4m3.f32 " \
    "{%0,%1,%2,%3}, {%4,%5,%6,%7}, {%8,%9}, {%0,%1,%2,%3};\n" \
    : "+f"((cc)[0]), "+f"((cc)[1]), "+f"((cc)[2]), "+f"((cc)[3]) \
    : "r"((aa)[0]), "r"((aa)[1]), "r"((aa)[2]), "r"((aa)[3]), "r"(b0), "r"(b1))

// ---------------------------------------------------------------------------
// Prep (prototypes only): fp32 rows -> e4m3 rows + exact fp32 row norms.
// ---------------------------------------------------------------------------
__global__ void prep_proto(const float* __restrict__ p) {
    int w = (blockIdx.x * blockDim.x + threadIdx.x) >> 5;
    int lane = threadIdx.x & 31;
    if (w >= PPTS) return;
    float2 v = ((const float2*)(p + (size_t)w * DDIM))[lane];
    float ss = v.x * v.x + v.y * v.y;
    #pragma unroll
    for (int o = 16; o; o >>= 1) ss += __shfl_xor_sync(0xffffffffu, ss, o);
    __nv_fp8x2_storage_t q = __nv_cvt_float2_to_fp8x2(v, __NV_SATFINITE, __NV_E4M3);
    *(unsigned short*)(g_pb + (size_t)w * DDIM + lane * 2) = (unsigned short)q;
    if (lane == 0) g_p2[w] = ss;
}

// ---------------------------------------------------------------------------
// Main: 256x128-tile e4m3 mma.sync (m16n8k32) GEMM fused with masked min +
// loss. 8 warps = 4(m) x 2(n); warp tile 64x64. MMA count and B LDS traffic
// are HALF of the bf16 variant; fp32 norms keep dist error ~1.8e-2 absolute.
// ---------------------------------------------------------------------------
__global__ __launch_bounds__(256, 2) void glvq_main(
    const float* __restrict__ x, const int* __restrict__ y,
    const int* __restrict__ plab, float* __restrict__ out) {

    extern __shared__ char sm[];
    const uint32_t smb = (uint32_t)__cvta_generic_to_shared(sm);
    float* red  = (float*)(sm + SM_RED);
    float* xs2  = (float*)(sm + SM_XS2);
    float* rsum = (float*)(sm + SM_RSUM);
    int*   flag = (int*)(sm + SM_FLAG);

    const int tid = threadIdx.x;
    const int warp = tid >> 5, lane = tid & 31;
    const int wm = warp >> 1, wn = warp & 1;   // 4 m-warps x 2 n-halves
    const int qid = lane >> 2, qtr = lane & 3;
    const int rowBase = blockIdx.x * BM;

    // Issue B0 tile + tile-0 metadata via cp.async (overlaps x converts).
    {
        #pragma unroll
        for (int i = 0; i < 2; i++) {
            int c = tid + i * 256;    // 512 chunks of 16B
            cp16(smb + SM_B0 + padoff(c), (const char*)g_pb + (size_t)c * 16);
        }
        if (tid < 32)      cp16(smb + SM_PP2 + tid * 16, (const char*)g_p2 + tid * 16);
        else if (tid < 64) cp16(smb + SM_PPL + (tid - 32) * 16,
                                (const char*)plab + (tid - 32) * 16);
        CP_COMMIT();
    }

    // A fragments for this warp's 64 rows: a[4 mf][2 kk][4] (32 regs).
    uint32_t a[4][2][4];
    const int arow = (lane & 7) + ((lane >> 3) & 1) * 8;
    const int acolB = (lane >> 4) * 16;        // byte column within 32B k-group

    // Two staging passes through SM_AB1: rows [0,128) then [128,256).
    #pragma unroll
    for (int stage = 0; stage < 2; stage++) {
        // Convert 128 rows fp32 -> e4m3 into SM_AB1; exact fp32 row norms.
        const int r = tid >> 1, h = tid & 1;   // 2 threads/row, 32 floats each
        const float4* xs4 = (const float4*)(
            x + (size_t)(rowBase + stage * 128 + r) * DDIM + h * 32);
        float ss = 0.f;
        uint32_t q[8];
        #pragma unroll
        for (int i = 0; i < 8; i++) {
            float4 v = xs4[i];
            ss += v.x * v.x + v.y * v.y + v.z * v.z + v.w * v.w;
            q[i] = pk8(v.x, v.y, v.z, v.w);
        }
        *(uint4*)(sm + SM_AB1 + r * ROWB + h * 32)      = make_uint4(q[0], q[1], q[2], q[3]);
        *(uint4*)(sm + SM_AB1 + r * ROWB + h * 32 + 16) = make_uint4(q[4], q[5], q[6], q[7]);
        ss += __shfl_xor_sync(0xffffffffu, ss, 1);
        if (h == 0) xs2[stage * 128 + r] = ss;
        __syncthreads();   // staged tile visible

        // Warps whose 64 rows live in this stage hoist their A fragments.
        if ((wm >> 1) == stage) {
            const int lrow = (wm & 1) * 64;    // row within the staged 128
            #pragma unroll
            for (int mf = 0; mf < 4; mf++)
                #pragma unroll
                for (int kk = 0; kk < 2; kk++) {
                    uint32_t ad = smb + SM_AB1
                        + (uint32_t)(lrow + mf * 16 + arow) * ROWB
                        + (uint32_t)(kk * 32 + acolB);
                    LDSMX4(a[mf][kk], ad);
                }
        }
        __syncthreads();   // A reads done before buffer reuse
    }

    // Row labels for this thread's 8 accumulator rows.
    int yv[4][2];
    #pragma unroll
    for (int mf = 0; mf < 4; mf++)
        #pragma unroll
        for (int h = 0; h < 2; h++)
            yv[mf][h] = y[rowBase + wm * 64 + mf * 16 + h * 8 + qid];

    float pmin[4][2], nmin[4][2];
    #pragma unroll
    for (int mf = 0; mf < 4; mf++)
        #pragma unroll
        for (int h = 0; h < 2; h++) { pmin[mf][h] = 1e30f; nmin[mf][h] = 1e30f; }

    const uint32_t brow_off = (uint32_t)(lane & 7) * ROWB + (uint32_t)((lane >> 3) & 3) * 16;

    for (int t = 0; t < NTILES; t++) {
        CP_WAIT(0);        // B[t] + meta[t] resident
        __syncthreads();   // visible to all; B[t-1] buffer free

        // Prefetch B[t+1] + meta[t+1] into the other buffer.
        if (t + 1 < NTILES) {
            const char* src = (const char*)(g_pb + (size_t)(t + 1) * BN * DDIM);
            uint32_t dstb = smb + (((t + 1) & 1) ? SM_AB1 : SM_B0);
            #pragma unroll
            for (int i = 0; i < 2; i++) {
                int c = tid + i * 256;
                cp16(dstb + padoff(c), src + (size_t)c * 16);
            }
            uint32_t mb = ((t + 1) & 1) * 512;
            if (tid < 32)
                cp16(smb + SM_PP2 + mb + tid * 16,
                     (const char*)(g_p2 + (size_t)(t + 1) * BN) + tid * 16);
            else if (tid < 64)
                cp16(smb + SM_PPL + mb + (tid - 32) * 16,
                     (const char*)(plab + (size_t)(t + 1) * BN) + (tid - 32) * 16);
            CP_COMMIT();
        }

        const int buf = t & 1;
        const uint32_t pbase = smb + (buf ? SM_AB1 : SM_B0)
                             + (uint32_t)(wn * 64) * ROWB + brow_off;
        const float* pp2 = (const float*)(sm + SM_PP2 + buf * 512);
        const int*   ppl = (const int*)(sm + SM_PPL + buf * 512);

        #pragma unroll
        for (int nf = 0; nf < 8; nf++) {
            // One ldmatrix.x4 covers the whole K=64 of this 8-proto slab.
            uint32_t b[4];
            LDSMX4(b, pbase + (uint32_t)(nf * 8) * ROWB);

            // 4 independent MMA chains (one per mf), depth 2.
            float c0[4] = {0.f, 0.f, 0.f, 0.f};
            float c1[4] = {0.f, 0.f, 0.f, 0.f};
            float c2[4] = {0.f, 0.f, 0.f, 0.f};
            float c3[4] = {0.f, 0.f, 0.f, 0.f};
            #pragma unroll
            for (int kk = 0; kk < 2; kk++) {
                MMAFP8(c0, a[0][kk], b[kk * 2], b[kk * 2 + 1]);
                MMAFP8(c1, a[1][kk], b[kk * 2], b[kk * 2 + 1]);
                MMAFP8(c2, a[2][kk], b[kk * 2], b[kk * 2 + 1]);
                MMAFP8(c3, a[3][kk], b[kk * 2], b[kk * 2 + 1]);
            }

            // Fused epilogue: s = p2 - 2*dot, masked running mins.
            const int jc = wn * 64 + nf * 8 + qtr * 2;
            float2 pp = *(const float2*)(pp2 + jc);
            int2   ll = *(const int2*)(ppl + jc);

            float* cs[4] = {c0, c1, c2, c3};
            #pragma unroll
            for (int mf = 0; mf < 4; mf++) {
                float s0 = fmaf(-2.f, cs[mf][0], pp.x);
                float s1 = fmaf(-2.f, cs[mf][1], pp.y);
                float s2 = fmaf(-2.f, cs[mf][2], pp.x);
                float s3 = fmaf(-2.f, cs[mf][3], pp.y);
                if (ll.x == yv[mf][0]) pmin[mf][0] = fminf(pmin[mf][0], s0);
                else                   nmin[mf][0] = fminf(nmin[mf][0], s0);
                if (ll.y == yv[mf][0]) pmin[mf][0] = fminf(pmin[mf][0], s1);
                else                   nmin[mf][0] = fminf(nmin[mf][0], s1);
                if (ll.x == yv[mf][1]) pmin[mf][1] = fminf(pmin[mf][1], s2);
                else                   nmin[mf][1] = fminf(nmin[mf][1], s2);
                if (ll.y == yv[mf][1]) pmin[mf][1] = fminf(pmin[mf][1], s3);
                else                   nmin[mf][1] = fminf(nmin[mf][1], s3);
            }
        }
    }

    // Quad reduction (same rows, different cols across 4 lanes).
    #pragma unroll
    for (int mf = 0; mf < 4; mf++)
        #pragma unroll
        for (int h = 0; h < 2; h++) {
            #pragma unroll
            for (int o = 1; o <= 2; o <<= 1) {
                pmin[mf][h] = fminf(pmin[mf][h], __shfl_xor_sync(0xffffffffu, pmin[mf][h], o));
                nmin[mf][h] = fminf(nmin[mf][h], __shfl_xor_sync(0xffffffffu, nmin[mf][h], o));
            }
        }
    __syncthreads();
    if (qtr == 0) {
        #pragma unroll
        for (int mf = 0; mf < 4; mf++)
            #pragma unroll
            for (int h = 0; h < 2; h++) {
                int r = wm * 64 + mf * 16 + h * 8 + qid;
                red[(wn * 2 + 0) * BM + r] = pmin[mf][h];
                red[(wn * 2 + 1) * BM + r] = nmin[mf][h];
            }
    }
    __syncthreads();

    // 256 rows, 256 threads: one per row.
    float spos = fminf(red[0 * BM + tid], red[2 * BM + tid]);
    float sneg = fminf(red[1 * BM + tid], red[3 * BM + tid]);
    float x2 = xs2[tid];
    float pos = sqrtf(fmaxf(spos + x2, 0.f));
    float neg = sqrtf(fmaxf(sneg + x2, 0.f));
    float mu = (pos - neg) / (pos + neg);
    float mysum = 1.f / (1.f + expf(-mu));
    #pragma unroll
    for (int o = 16; o; o >>= 1) mysum += __shfl_xor_sync(0xffffffffu, mysum, o);
    if (lane == 0) rsum[warp] = mysum;
    __syncthreads();
    if (tid == 0) {
        float s = 0.f;
        #pragma unroll
        for (int i = 0; i < 8; i++) s += rsum[i];
        g_partial[blockIdx.x] = s;
        __threadfence();
        unsigned int ticket = atomicAdd(&g_count, 1);
        *flag = (ticket == gridDim.x - 1) ? 1 : 0;
    }
    __syncthreads();

    if (*flag) {   // last block: deterministic final mean
        float s = __ldcg(&g_partial[tid]);   // NBLOCKS == blockDim.x == 256
        #pragma unroll
        for (int o = 16; o; o >>= 1) s += __shfl_xor_sync(0xffffffffu, s, o);
        if (lane == 0) rsum[warp] = s;
        __syncthreads();
        if (tid == 0) {
            float tot = 0.f;
            #pragma unroll
            for (int i = 0; i < 8; i++) tot += rsum[i];
            out[0] = tot * (1.0f / (float)NPTS);
            g_count = 0;   // reset for next graph replay
        }
    }
}

extern "C" void kernel_launch(void* const* d_in, const int* in_sizes, int n_in,
                              void* d_out, int out_size) {
    const float* x    = (const float*)d_in[0];
    const int*   yy   = (const int*)d_in[1];
    const float* prot = (const float*)d_in[2];
    const int*   plab = (const int*)d_in[3];
    float* out = (float*)d_out;

    cudaFuncSetAttribute(glvq_main, cudaFuncAttributeMaxDynamicSharedMemorySize, SM_TOTAL);

    prep_proto<<<PPTS / 8, 256>>>(prot);
    glvq_main<<<NBLOCKS, 256, SM_TOTAL>>>(x, yy, plab, out);
}

// round 16
// speedup vs baseline: 1.2406x; 1.2406x over previous
#include <cuda_runtime.h>
#include <cuda_bf16.h>
#include <math.h>
#include <stdint.h>

// Shape (fixed by dataset): N=65536, P=2048, D=64, 10 classes.
#define NPTS 65536
#define PPTS 2048
#define DDIM 64
#define BM 256               // two 128-row x-tiles per CTA
#define BN 128
#define LDSS 72              // bf16 per smem row (64 + 8 pad): conflict-free ldmatrix
#define ROWB (LDSS * 2)      // 144 bytes per padded row
#define NTILES (PPTS / BN)   // 16
#define NBLOCKS (NPTS / BM)  // 256  (2 CTAs/SM x 148 SMs = 296 >= 256: co-resident)

// __device__ scratch (allocation-free rule).
__device__ __align__(16) __nv_bfloat16 g_pb[PPTS * DDIM];
__device__ __align__(16) float g_p2[PPTS];
__device__ float g_partial[NBLOCKS];
__device__ unsigned int g_count;   // end-of-kernel ticket; last block resets
__device__ unsigned int g_sync;    // proto-conversion barrier; last block resets

// Dynamic smem layout (bytes)
#define SM_B0    0                 // B tile buffer (even t)          18432
#define SM_AB1   18432             // x-convert staging, then B buf   18432
#define SM_PP2   36864             // 2 bufs x 128 f32                 1024
#define SM_PPL   37888             // 2 bufs x 128 i32                 1024
#define SM_RED   38912             // [2 wn][2][256] f32               8192
#define SM_XS2   47104             // 256 f32 row norms                1024
#define SM_RSUM  48128             // 8 f32
#define SM_FLAG  48160
#define SM_TOTAL 48192

__device__ __forceinline__ void cp16(uint32_t dst, const void* src) {
    asm volatile("cp.async.cg.shared.global [%0], [%1], 16;\n" :: "r"(dst), "l"(src));
}
#define CP_COMMIT() asm volatile("cp.async.commit_group;\n" ::: "memory")
#define CP_WAIT(n)  asm volatile("cp.async.wait_group %0;\n" :: "n"(n) : "memory")

__device__ __forceinline__ uint32_t padoff(int idx) {     // idx-th 16B chunk
    return (uint32_t)((idx >> 3) * ROWB + (idx & 7) * 16);
}
__device__ __forceinline__ uint32_t pk2(float a, float b) {
    __nv_bfloat162 t = __floats2bfloat162_rn(a, b);
    return *(uint32_t*)&t;
}
#define LDSMX4(rr, addr) asm volatile( \
    "ldmatrix.sync.aligned.m8n8.x4.shared.b16 {%0,%1,%2,%3}, [%4];\n" \
    : "=r"((rr)[0]), "=r"((rr)[1]), "=r"((rr)[2]), "=r"((rr)[3]) : "r"(addr))
#define MMA16816(cc, aa, b0, b1) asm volatile( \
    "mma.sync.aligned.m16n8k16.row.col.f32.bf16.bf16.f32 " \
    "{%0,%1,%2,%3}, {%4,%5,%6,%7}, {%8,%9}, {%0,%1,%2,%3};\n" \
    : "+f"((cc)[0]), "+f"((cc)[1]), "+f"((cc)[2]), "+f"((cc)[3]) \
    : "r"((aa)[0]), "r"((aa)[1]), "r"((aa)[2]), "r"((aa)[3]), "r"(b0), "r"(b1))

// ---------------------------------------------------------------------------
// Single fused kernel. Phase 0: each CTA converts 8 prototypes (warp/row)
// and arrives on g_sync. Phase 1: x-convert + A-frag hoist (overlaps the
// other CTAs' phase 0). Spin until all protos ready, then the tile loop.
// ---------------------------------------------------------------------------
__global__ __launch_bounds__(256, 2) void glvq_main(
    const float* __restrict__ x, const int* __restrict__ y,
    const float* __restrict__ prot, const int* __restrict__ plab,
    float* __restrict__ out) {

    extern __shared__ char sm[];
    const uint32_t smb = (uint32_t)__cvta_generic_to_shared(sm);
    float* red  = (float*)(sm + SM_RED);
    float* xs2  = (float*)(sm + SM_XS2);
    float* rsum = (float*)(sm + SM_RSUM);
    int*   flag = (int*)(sm + SM_FLAG);

    const int tid = threadIdx.x;
    const int warp = tid >> 5, lane = tid & 31;
    const int wm = warp >> 1, wn = warp & 1;   // 4 m-warps x 2 n-halves
    const int qid = lane >> 2, qtr = lane & 3;
    const int rowBase = blockIdx.x * BM;

    // ---- Phase 0: convert this CTA's 8 prototypes (warp per row) ----
    {
        const int pj = blockIdx.x * 8 + warp;    // 256 CTAs x 8 = 2048
        float2 v = ((const float2*)(prot + (size_t)pj * DDIM))[lane];
        float ss = v.x * v.x + v.y * v.y;
        #pragma unroll
        for (int o = 16; o; o >>= 1) ss += __shfl_xor_sync(0xffffffffu, ss, o);
        ((__nv_bfloat162*)g_pb)[(size_t)pj * (DDIM / 2) + lane] =
            __floats2bfloat162_rn(v.x, v.y);
        if (lane == 0) g_p2[pj] = ss;
    }
    __syncthreads();
    if (tid == 0) {
        __threadfence();                         // publish proto writes
        atomicAdd(&g_sync, 1u);
    }

    // ---- Phase 1: x tile convert + A fragment hoist (no proto dependency) --
    uint32_t a[4][4][4];
    const int arow = (lane & 7) + ((lane >> 3) & 1) * 8;
    const int acol = (lane >> 4) * 8;

    #pragma unroll
    for (int stage = 0; stage < 2; stage++) {
        const int r = tid >> 1, h = tid & 1;
        const float4* xs4 = (const float4*)(
            x + (size_t)(rowBase + stage * 128 + r) * DDIM + h * 32);
        float ss = 0.f;
        #pragma unroll
        for (int i = 0; i < 4; i++) {
            float4 v0 = xs4[i * 2], v1 = xs4[i * 2 + 1];
            ss += v0.x * v0.x + v0.y * v0.y + v0.z * v0.z + v0.w * v0.w
                + v1.x * v1.x + v1.y * v1.y + v1.z * v1.z + v1.w * v1.w;
            uint4 w;
            w.x = pk2(v0.x, v0.y); w.y = pk2(v0.z, v0.w);
            w.z = pk2(v1.x, v1.y); w.w = pk2(v1.z, v1.w);
            *(uint4*)(sm + SM_AB1 + r * ROWB + h * 64 + i * 16) = w;
        }
        ss += __shfl_xor_sync(0xffffffffu, ss, 1);
        if (h == 0) xs2[stage * 128 + r] = ss;
        __syncthreads();   // staged tile visible

        if ((wm >> 1) == stage) {
            const int lrow = (wm & 1) * 64;      // row within the staged 128
            #pragma unroll
            for (int mf = 0; mf < 4; mf++)
                #pragma unroll
                for (int kk = 0; kk < 4; kk++) {
                    uint32_t ad = smb + SM_AB1
                        + (uint32_t)(lrow + mf * 16 + arow) * ROWB
                        + (uint32_t)(kk * 16 + acol) * 2;
                    LDSMX4(a[mf][kk], ad);
                }
        }
        __syncthreads();   // A reads done before buffer reuse
    }

    // Row labels for this thread's 8 accumulator rows.
    int yv[4][2];
    #pragma unroll
    for (int mf = 0; mf < 4; mf++)
        #pragma unroll
        for (int h = 0; h < 2; h++)
            yv[mf][h] = y[rowBase + wm * 64 + mf * 16 + h * 8 + qid];

    float pmin[4][2], nmin[4][2];
    #pragma unroll
    for (int mf = 0; mf < 4; mf++)
        #pragma unroll
        for (int h = 0; h < 2; h++) { pmin[mf][h] = 1e30f; nmin[mf][h] = 1e30f; }

    // ---- Grid barrier: all prototypes converted (usually already true) ----
    if (tid == 0) {
        while (*(volatile unsigned int*)&g_sync < (unsigned int)NBLOCKS)
            __nanosleep(64);
        __threadfence();                         // acquire proto writes
    }
    __syncthreads();

    // Issue B0 tile + tile-0 metadata via cp.async.
    {
        #pragma unroll
        for (int i = 0; i < 4; i++) {
            int c = tid + i * 256;
            cp16(smb + SM_B0 + padoff(c), (const char*)g_pb + (size_t)c * 16);
        }
        if (tid < 32)      cp16(smb + SM_PP2 + tid * 16, (const char*)g_p2 + tid * 16);
        else if (tid < 64) cp16(smb + SM_PPL + (tid - 32) * 16,
                                (const char*)plab + (tid - 32) * 16);
        CP_COMMIT();
    }

    const uint32_t brow_off = (uint32_t)(lane & 7) * ROWB + (uint32_t)((lane >> 3) & 3) * 16;

    for (int t = 0; t < NTILES; t++) {
        CP_WAIT(0);        // B[t] + meta[t] resident
        __syncthreads();   // visible to all; B[t-1] buffer free

        // Prefetch B[t+1] + meta[t+1] into the other buffer.
        if (t + 1 < NTILES) {
            const char* src = (const char*)(g_pb + (size_t)(t + 1) * BN * DDIM);
            uint32_t dstb = smb + (((t + 1) & 1) ? SM_AB1 : SM_B0);
            #pragma unroll
            for (int i = 0; i < 4; i++) {
                int c = tid + i * 256;
                cp16(dstb + padoff(c), src + (size_t)c * 16);
            }
            uint32_t mb = ((t + 1) & 1) * 512;
            if (tid < 32)
                cp16(smb + SM_PP2 + mb + tid * 16,
                     (const char*)(g_p2 + (size_t)(t + 1) * BN) + tid * 16);
            else if (tid < 64)
                cp16(smb + SM_PPL + mb + (tid - 32) * 16,
                     (const char*)(plab + (size_t)(t + 1) * BN) + (tid - 32) * 16);
            CP_COMMIT();
        }

        const int buf = t & 1;
        const uint32_t pbase = smb + (buf ? SM_AB1 : SM_B0)
                             + (uint32_t)(wn * 64) * ROWB + brow_off;
        const float* pp2 = (const float*)(sm + SM_PP2 + buf * 512);
        const int*   ppl = (const int*)(sm + SM_PPL + buf * 512);

        #pragma unroll
        for (int nf = 0; nf < 8; nf++) {
            uint32_t b[8];
            uint32_t r0 = pbase + (uint32_t)(nf * 8) * ROWB;
            LDSMX4(b,     r0);
            LDSMX4(b + 4, r0 + 64);

            // 4 independent MMA chains (one per mf), each depth 4.
            float c0[4] = {0.f, 0.f, 0.f, 0.f};
            float c1[4] = {0.f, 0.f, 0.f, 0.f};
            float c2[4] = {0.f, 0.f, 0.f, 0.f};
            float c3[4] = {0.f, 0.f, 0.f, 0.f};
            #pragma unroll
            for (int kk = 0; kk < 4; kk++) {
                MMA16816(c0, a[0][kk], b[kk * 2], b[kk * 2 + 1]);
                MMA16816(c1, a[1][kk], b[kk * 2], b[kk * 2 + 1]);
                MMA16816(c2, a[2][kk], b[kk * 2], b[kk * 2 + 1]);
                MMA16816(c3, a[3][kk], b[kk * 2], b[kk * 2 + 1]);
            }

            // Fused epilogue: s = p2 - 2*dot, masked running mins.
            const int jc = wn * 64 + nf * 8 + qtr * 2;
            float2 pp = *(const float2*)(pp2 + jc);
            int2   ll = *(const int2*)(ppl + jc);

            float* cs[4] = {c0, c1, c2, c3};
            #pragma unroll
            for (int mf = 0; mf < 4; mf++) {
                float s0 = fmaf(-2.f, cs[mf][0], pp.x);
                float s1 = fmaf(-2.f, cs[mf][1], pp.y);
                float s2 = fmaf(-2.f, cs[mf][2], pp.x);
                float s3 = fmaf(-2.f, cs[mf][3], pp.y);
                if (ll.x == yv[mf][0]) pmin[mf][0] = fminf(pmin[mf][0], s0);
                else                   nmin[mf][0] = fminf(nmin[mf][0], s0);
                if (ll.y == yv[mf][0]) pmin[mf][0] = fminf(pmin[mf][0], s1);
                else                   nmin[mf][0] = fminf(nmin[mf][0], s1);
                if (ll.x == yv[mf][1]) pmin[mf][1] = fminf(pmin[mf][1], s2);
                else                   nmin[mf][1] = fminf(nmin[mf][1], s2);
                if (ll.y == yv[mf][1]) pmin[mf][1] = fminf(pmin[mf][1], s3);
                else                   nmin[mf][1] = fminf(nmin[mf][1], s3);
            }
        }
    }

    // Quad reduction (same rows, different cols across 4 lanes).
    #pragma unroll
    for (int mf = 0; mf < 4; mf++)
        #pragma unroll
        for (int h = 0; h < 2; h++) {
            #pragma unroll
            for (int o = 1; o <= 2; o <<= 1) {
                pmin[mf][h] = fminf(pmin[mf][h], __shfl_xor_sync(0xffffffffu, pmin[mf][h], o));
                nmin[mf][h] = fminf(nmin[mf][h], __shfl_xor_sync(0xffffffffu, nmin[mf][h], o));
            }
        }
    __syncthreads();
    if (qtr == 0) {
        #pragma unroll
        for (int mf = 0; mf < 4; mf++)
            #pragma unroll
            for (int h = 0; h < 2; h++) {
                int r = wm * 64 + mf * 16 + h * 8 + qid;
                red[(wn * 2 + 0) * BM + r] = pmin[mf][h];
                red[(wn * 2 + 1) * BM + r] = nmin[mf][h];
            }
    }
    __syncthreads();

    // 256 rows, 256 threads: one per row.
    float spos = fminf(red[0 * BM + tid], red[2 * BM + tid]);
    float sneg = fminf(red[1 * BM + tid], red[3 * BM + tid]);
    float x2 = xs2[tid];
    float pos = sqrtf(fmaxf(spos + x2, 0.f));
    float neg = sqrtf(fmaxf(sneg + x2, 0.f));
    float mu = (pos - neg) / (pos + neg);
    float mysum = 1.f / (1.f + expf(-mu));
    #pragma unroll
    for (int o = 16; o; o >>= 1) mysum += __shfl_xor_sync(0xffffffffu, mysum, o);
    if (lane == 0) rsum[warp] = mysum;
    __syncthreads();
    if (tid == 0) {
        float s = 0.f;
        #pragma unroll
        for (int i = 0; i < 8; i++) s += rsum[i];
        g_partial[blockIdx.x] = s;
        __threadfence();
        unsigned int ticket = atomicAdd(&g_count, 1);
        *flag = (ticket == gridDim.x - 1) ? 1 : 0;
    }
    __syncthreads();

    if (*flag) {   // last block: deterministic final mean + counter resets
        float s = __ldcg(&g_partial[tid]);   // NBLOCKS == blockDim.x == 256
        #pragma unroll
        for (int o = 16; o; o >>= 1) s += __shfl_xor_sync(0xffffffffu, s, o);
        if (lane == 0) rsum[warp] = s;
        __syncthreads();
        if (tid == 0) {
            float tot = 0.f;
            #pragma unroll
            for (int i = 0; i < 8; i++) tot += rsum[i];
            out[0] = tot * (1.0f / (float)NPTS);
            g_count = 0;   // reset for next graph replay
            g_sync  = 0;   // all CTAs are long past the spin (they all arrived
                           // at g_count before this block ran) — safe to reset
        }
    }
}

extern "C" void kernel_launch(void* const* d_in, const int* in_sizes, int n_in,
                              void* d_out, int out_size) {
    const float* x    = (const float*)d_in[0];
    const int*   yy   = (const int*)d_in[1];
    const float* prot = (const float*)d_in[2];
    const int*   plab = (const int*)d_in[3];
    float* out = (float*)d_out;

    cudaFuncSetAttribute(glvq_main, cudaFuncAttributeMaxDynamicSharedMemorySize, SM_TOTAL);

    glvq_main<<<NBLOCKS, 256, SM_TOTAL>>>(x, yy, prot, plab, out);
}

// round 17
// speedup vs baseline: 1.2747x; 1.0275x over previous
#include <cuda_runtime.h>
#include <cuda_bf16.h>
#include <math.h>
#include <stdint.h>

// Shape (fixed by dataset): N=65536, P=2048, D=64, 10 classes.
#define NPTS 65536
#define PPTS 2048
#define DDIM 64
#define BN 128
#define LDSS 72              // bf16 per smem row (64 + 8 pad): conflict-free ldmatrix
#define ROWB (LDSS * 2)      // 144 bytes per padded row
#define NTILES (PPTS / BN)   // 16
#define NBLOCKS 296          // 2 CTAs/SM x 148 SMs: ALL co-resident
#define NBIG 136             // CTAs with BM=256 (b<136); rest BM=192
// 136*256 + 160*192 = 65536. Pairing (b, b+148) => 136 SMs get 256+192=448
// rows, 12 SMs get 192+192=384: finish = 448/442.8 = +1.2% vs +15.6% before.

// __device__ scratch (allocation-free rule).
__device__ __align__(16) __nv_bfloat16 g_pb[PPTS * DDIM];
__device__ __align__(16) float g_p2[PPTS];
__device__ float g_partial[NBLOCKS];
__device__ unsigned int g_count;   // end-of-kernel ticket; last block resets
__device__ unsigned int g_sync;    // proto-conversion barrier; last block resets

// Dynamic smem layout (bytes)  (same offsets as the 68.1us kernel)
#define SM_B0    0                 // B tile buffer (even t)          18432
#define SM_AB1   18432             // x staging (<=128 rows) / B buf  18432
#define SM_PP2   36864             // 2 bufs x 128 f32                 1024
#define SM_PPL   37888             // 2 bufs x 128 i32                 1024
#define SM_RED   38912             // [2 wn][2][256] f32 (+slack)      8192
#define SM_XS2   47104             // 256 f32 row norms                1024
#define SM_RSUM  48128             // 8 f32
#define SM_FLAG  48160
#define SM_TOTAL 48192

__device__ __forceinline__ void cp16(uint32_t dst, const void* src) {
    asm volatile("cp.async.cg.shared.global [%0], [%1], 16;\n" :: "r"(dst), "l"(src));
}
#define CP_COMMIT() asm volatile("cp.async.commit_group;\n" ::: "memory")
#define CP_WAIT(n)  asm volatile("cp.async.wait_group %0;\n" :: "n"(n) : "memory")

__device__ __forceinline__ uint32_t padoff(int idx) {     // idx-th 16B chunk
    return (uint32_t)((idx >> 3) * ROWB + (idx & 7) * 16);
}
__device__ __forceinline__ uint32_t pk2(float a, float b) {
    __nv_bfloat162 t = __floats2bfloat162_rn(a, b);
    return *(uint32_t*)&t;
}
#define LDSMX4(rr, addr) asm volatile( \
    "ldmatrix.sync.aligned.m8n8.x4.shared.b16 {%0,%1,%2,%3}, [%4];\n" \
    : "=r"((rr)[0]), "=r"((rr)[1]), "=r"((rr)[2]), "=r"((rr)[3]) : "r"(addr))
#define MMA16816(cc, aa, b0, b1) asm volatile( \
    "mma.sync.aligned.m16n8k16.row.col.f32.bf16.bf16.f32 " \
    "{%0,%1,%2,%3}, {%4,%5,%6,%7}, {%8,%9}, {%0,%1,%2,%3};\n" \
    : "+f"((cc)[0]), "+f"((cc)[1]), "+f"((cc)[2]), "+f"((cc)[3]) \
    : "r"((aa)[0]), "r"((aa)[1]), "r"((aa)[2]), "r"((aa)[3]), "r"(b0), "r"(b1))

// ---------------------------------------------------------------------------
// Single fused kernel, mixed-BM grid for SM load balance.
// Phase 0: each CTA converts 7 prototypes. Phase 1: x convert + A hoist
// (overlaps other CTAs' phase 0). Spin, then the 16-tile GEMM+min loop.
// ---------------------------------------------------------------------------
__global__ __launch_bounds__(256, 2) void glvq_main(
    const float* __restrict__ x, const int* __restrict__ y,
    const float* __restrict__ prot, const int* __restrict__ plab,
    float* __restrict__ out) {

    extern __shared__ char sm[];
    const uint32_t smb = (uint32_t)__cvta_generic_to_shared(sm);
    float* red  = (float*)(sm + SM_RED);
    float* xs2  = (float*)(sm + SM_XS2);
    float* rsum = (float*)(sm + SM_RSUM);
    int*   flag = (int*)(sm + SM_FLAG);

    const int tid = threadIdx.x;
    const int warp = tid >> 5, lane = tid & 31;
    const int wm = warp >> 1, wn = warp & 1;   // 4 m-warps x 2 n-halves
    const int qid = lane >> 2, qtr = lane & 3;

    const int b = blockIdx.x;
    const bool big = (b < NBIG);
    const int BMb     = big ? 256 : 192;
    const int MF      = big ? 4 : 3;           // m-tiles per warp (uniform)
    const int rowBase = big ? b * 256 : NBIG * 256 + (b - NBIG) * 192;

    // ---- Phase 0: convert this CTA's prototypes (7 rows, warp per row) ----
    if (warp < 7) {
        const int pj = b * 7 + warp;           // 296*7 = 2072 >= 2048
        if (pj < PPTS) {
            float2 v = ((const float2*)(prot + (size_t)pj * DDIM))[lane];
            float ss = v.x * v.x + v.y * v.y;
            #pragma unroll
            for (int o = 16; o; o >>= 1) ss += __shfl_xor_sync(0xffffffffu, ss, o);
            ((__nv_bfloat162*)g_pb)[(size_t)pj * (DDIM / 2) + lane] =
                __floats2bfloat162_rn(v.x, v.y);
            if (lane == 0) g_p2[pj] = ss;
        }
    }
    __syncthreads();
    if (tid == 0) {
        __threadfence();                       // publish proto writes
        atomicAdd(&g_sync, 1u);
    }

    // ---- Phase 1: x convert + A fragment hoist (chunks of <=128 rows) ----
    uint32_t a[4][4][4];                       // [mf<=4][kk][4]
    const int arow = (lane & 7) + ((lane >> 3) & 1) * 8;
    const int acol = (lane >> 4) * 8;

    for (int base = 0; base < BMb; base += 128) {
        const int cr = min(128, BMb - base);   // rows in this chunk
        const int r = tid >> 1, h = tid & 1;
        if (r < cr) {
            const float4* xs4 = (const float4*)(
                x + (size_t)(rowBase + base + r) * DDIM + h * 32);
            float ss = 0.f;
            #pragma unroll
            for (int i = 0; i < 4; i++) {
                float4 v0 = xs4[i * 2], v1 = xs4[i * 2 + 1];
                ss += v0.x * v0.x + v0.y * v0.y + v0.z * v0.z + v0.w * v0.w
                    + v1.x * v1.x + v1.y * v1.y + v1.z * v1.z + v1.w * v1.w;
                uint4 w;
                w.x = pk2(v0.x, v0.y); w.y = pk2(v0.z, v0.w);
                w.z = pk2(v1.x, v1.y); w.w = pk2(v1.z, v1.w);
                *(uint4*)(sm + SM_AB1 + r * ROWB + h * 64 + i * 16) = w;
            }
            ss += __shfl_xor_sync(0xffffffffu, ss, 1);
            if (h == 0) xs2[base + r] = ss;
        }
        __syncthreads();   // staged chunk visible

        // Hoist this warp's m-tiles that live in this chunk.
        #pragma unroll
        for (int mf = 0; mf < 4; mf++) {
            if (mf >= MF) continue;
            const int tr = (wm * MF + mf) * 16 - base;   // row within chunk
            if (tr >= 0 && tr < cr) {
                #pragma unroll
                for (int kk = 0; kk < 4; kk++) {
                    uint32_t ad = smb + SM_AB1
                        + (uint32_t)(tr + arow) * ROWB
                        + (uint32_t)(kk * 16 + acol) * 2;
                    LDSMX4(a[mf][kk], ad);
                }
            }
        }
        __syncthreads();   // A reads done before buffer reuse
    }

    // Row labels for this thread's accumulator rows.
    int yv[4][2];
    #pragma unroll
    for (int mf = 0; mf < 4; mf++)
        #pragma unroll
        for (int h = 0; h < 2; h++)
            yv[mf][h] = (mf < MF)
                ? y[rowBase + (wm * MF + mf) * 16 + h * 8 + qid] : 0;

    float pmin[4][2], nmin[4][2];
    #pragma unroll
    for (int mf = 0; mf < 4; mf++)
        #pragma unroll
        for (int h = 0; h < 2; h++) { pmin[mf][h] = 1e30f; nmin[mf][h] = 1e30f; }

    // ---- Grid barrier: all prototypes converted (usually already true) ----
    if (tid == 0) {
        while (*(volatile unsigned int*)&g_sync < (unsigned int)NBLOCKS)
            __nanosleep(64);
        __threadfence();                       // acquire proto writes
    }
    __syncthreads();

    // Issue B0 tile + tile-0 metadata via cp.async.
    {
        #pragma unroll
        for (int i = 0; i < 4; i++) {
            int c = tid + i * 256;
            cp16(smb + SM_B0 + padoff(c), (const char*)g_pb + (size_t)c * 16);
        }
        if (tid < 32)      cp16(smb + SM_PP2 + tid * 16, (const char*)g_p2 + tid * 16);
        else if (tid < 64) cp16(smb + SM_PPL + (tid - 32) * 16,
                                (const char*)plab + (tid - 32) * 16);
        CP_COMMIT();
    }

    const uint32_t brow_off = (uint32_t)(lane & 7) * ROWB + (uint32_t)((lane >> 3) & 3) * 16;

    for (int t = 0; t < NTILES; t++) {
        CP_WAIT(0);        // B[t] + meta[t] resident
        __syncthreads();   // visible to all; B[t-1] buffer free

        // Prefetch B[t+1] + meta[t+1] into the other buffer.
        if (t + 1 < NTILES) {
            const char* src = (const char*)(g_pb + (size_t)(t + 1) * BN * DDIM);
            uint32_t dstb = smb + (((t + 1) & 1) ? SM_AB1 : SM_B0);
            #pragma unroll
            for (int i = 0; i < 4; i++) {
                int c = tid + i * 256;
                cp16(dstb + padoff(c), src + (size_t)c * 16);
            }
            uint32_t mb = ((t + 1) & 1) * 512;
            if (tid < 32)
                cp16(smb + SM_PP2 + mb + tid * 16,
                     (const char*)(g_p2 + (size_t)(t + 1) * BN) + tid * 16);
            else if (tid < 64)
                cp16(smb + SM_PPL + mb + (tid - 32) * 16,
                     (const char*)(plab + (size_t)(t + 1) * BN) + (tid - 32) * 16);
            CP_COMMIT();
        }

        const int buf = t & 1;
        const uint32_t pbase = smb + (buf ? SM_AB1 : SM_B0)
                             + (uint32_t)(wn * 64) * ROWB + brow_off;
        const float* pp2 = (const float*)(sm + SM_PP2 + buf * 512);
        const int*   ppl = (const int*)(sm + SM_PPL + buf * 512);

        #pragma unroll
        for (int nf = 0; nf < 8; nf++) {
            uint32_t bfr[8];
            uint32_t r0 = pbase + (uint32_t)(nf * 8) * ROWB;
            LDSMX4(bfr,     r0);
            LDSMX4(bfr + 4, r0 + 64);

            // Up to 4 independent MMA chains (one per m-tile), depth 4.
            float c0[4] = {0.f, 0.f, 0.f, 0.f};
            float c1[4] = {0.f, 0.f, 0.f, 0.f};
            float c2[4] = {0.f, 0.f, 0.f, 0.f};
            float c3[4] = {0.f, 0.f, 0.f, 0.f};
            #pragma unroll
            for (int kk = 0; kk < 4; kk++) {
                MMA16816(c0, a[0][kk], bfr[kk * 2], bfr[kk * 2 + 1]);
                MMA16816(c1, a[1][kk], bfr[kk * 2], bfr[kk * 2 + 1]);
                MMA16816(c2, a[2][kk], bfr[kk * 2], bfr[kk * 2 + 1]);
            }
            if (MF == 4) {
                #pragma unroll
                for (int kk = 0; kk < 4; kk++)
                    MMA16816(c3, a[3][kk], bfr[kk * 2], bfr[kk * 2 + 1]);
            }

            // Fused epilogue: s = p2 - 2*dot, masked running mins.
            const int jc = wn * 64 + nf * 8 + qtr * 2;
            float2 pp = *(const float2*)(pp2 + jc);
            int2   ll = *(const int2*)(ppl + jc);

            float* cs[4] = {c0, c1, c2, c3};
            #pragma unroll
            for (int mf = 0; mf < 4; mf++) {
                if (mf >= MF) continue;
                float s0 = fmaf(-2.f, cs[mf][0], pp.x);
                float s1 = fmaf(-2.f, cs[mf][1], pp.y);
                float s2 = fmaf(-2.f, cs[mf][2], pp.x);
                float s3 = fmaf(-2.f, cs[mf][3], pp.y);
                if (ll.x == yv[mf][0]) pmin[mf][0] = fminf(pmin[mf][0], s0);
                else                   nmin[mf][0] = fminf(nmin[mf][0], s0);
                if (ll.y == yv[mf][0]) pmin[mf][0] = fminf(pmin[mf][0], s1);
                else                   nmin[mf][0] = fminf(nmin[mf][0], s1);
                if (ll.x == yv[mf][1]) pmin[mf][1] = fminf(pmin[mf][1], s2);
                else                   nmin[mf][1] = fminf(nmin[mf][1], s2);
                if (ll.y == yv[mf][1]) pmin[mf][1] = fminf(pmin[mf][1], s3);
                else                   nmin[mf][1] = fminf(nmin[mf][1], s3);
            }
        }
    }

    // Quad reduction (same rows, different cols across 4 lanes).
    #pragma unroll
    for (int mf = 0; mf < 4; mf++)
        #pragma unroll
        for (int h = 0; h < 2; h++) {
            #pragma unroll
            for (int o = 1; o <= 2; o <<= 1) {
                pmin[mf][h] = fminf(pmin[mf][h], __shfl_xor_sync(0xffffffffu, pmin[mf][h], o));
                nmin[mf][h] = fminf(nmin[mf][h], __shfl_xor_sync(0xffffffffu, nmin[mf][h], o));
            }
        }
    __syncthreads();
    if (qtr == 0) {
        #pragma unroll
        for (int mf = 0; mf < 4; mf++) {
            if (mf >= MF) continue;
            #pragma unroll
            for (int h = 0; h < 2; h++) {
                int r = (wm * MF + mf) * 16 + h * 8 + qid;
                red[(wn * 2 + 0) * 256 + r] = pmin[mf][h];
                red[(wn * 2 + 1) * 256 + r] = nmin[mf][h];
            }
        }
    }
    __syncthreads();

    // One thread per row (tid < BMb).
    float mysum = 0.f;
    if (tid < BMb) {
        float spos = fminf(red[0 * 256 + tid], red[2 * 256 + tid]);
        float sneg = fminf(red[1 * 256 + tid], red[3 * 256 + tid]);
        float x2 = xs2[tid];
        float pos = sqrtf(fmaxf(spos + x2, 0.f));
        float neg = sqrtf(fmaxf(sneg + x2, 0.f));
        float mu = (pos - neg) / (pos + neg);
        mysum = 1.f / (1.f + expf(-mu));
    }
    #pragma unroll
    for (int o = 16; o; o >>= 1) mysum += __shfl_xor_sync(0xffffffffu, mysum, o);
    if (lane == 0) rsum[warp] = mysum;
    __syncthreads();
    if (tid == 0) {
        float s = 0.f;
        #pragma unroll
        for (int i = 0; i < 8; i++) s += rsum[i];
        g_partial[b] = s;
        __threadfence();
        unsigned int ticket = atomicAdd(&g_count, 1);
        *flag = (ticket == gridDim.x - 1) ? 1 : 0;
    }
    __syncthreads();

    if (*flag) {   // last block: deterministic final mean + counter resets
        float s = 0.f;
        for (int i = tid; i < NBLOCKS; i += 256) s += __ldcg(&g_partial[i]);
        #pragma unroll
        for (int o = 16; o; o >>= 1) s += __shfl_xor_sync(0xffffffffu, s, o);
        if (lane == 0) rsum[warp] = s;
        __syncthreads();
        if (tid == 0) {
            float tot = 0.f;
            #pragma unroll
            for (int i = 0; i < 8; i++) tot += rsum[i];
            out[0] = tot * (1.0f / (float)NPTS);
            g_count = 0;   // reset for next graph replay
            g_sync  = 0;   // all CTAs are past the spin (co-resident) — safe
        }
    }
}

extern "C" void kernel_launch(void* const* d_in, const int* in_sizes, int n_in,
                              void* d_out, int out_size) {
    const float* x    = (const float*)d_in[0];
    const int*   yy   = (const int*)d_in[1];
    const float* prot = (const float*)d_in[2];
    const int*   plab = (const int*)d_in[3];
    float* out = (float*)d_out;

    cudaFuncSetAttribute(glvq_main, cudaFuncAttributeMaxDynamicSharedMemorySize, SM_TOTAL);

    glvq_main<<<NBLOCKS, 256, SM_TOTAL>>>(x, yy, prot, plab, out);
}